// round 2
// baseline (speedup 1.0000x reference)
#include <cuda_runtime.h>
#include <cuda_fp16.h>
#include <cstdint>

// ---------------- problem constants ----------------
#define B_ROWS   524288
#define N_TASKS  16384          // 32 rows per warp-task
#define THREADS  256            // 8 warps
#define GRID_CTAS 296

// smem layout (bytes)
#define OFF_BFRAG 0u            // 2048 x uint4 = 32768  (W1 fp16 B-fragments)
#define OFF_B1F   32768u        // 256 x uint4 = 4096    (b1 f16x2 frags)
#define OFF_W2F   36864u        // 256 x uint4 = 4096    (W2 f16x2 frags)
#define OFF_XST   40960u        // 8 warps x 4608B x-stage / out-stage
#define XST_STRIDE 4608u
#define SMEM_BYTES 77824u

static __device__ unsigned int g_task_ctr;

// ---------------- helpers ----------------
// pack two f32 -> f16x2 {lo, hi}
__device__ __forceinline__ uint32_t pack_h2(float lo, float hi) {
    uint32_t r;
    asm("cvt.rn.f16x2.f32 %0, %1, %2;" : "=r"(r) : "f"(hi), "f"(lo));
    return r;
}
__device__ __forceinline__ uint32_t tanh2u(uint32_t v) {
    uint32_t r;
    asm("tanh.approx.f16x2 %0, %1;" : "=r"(r) : "r"(v));
    return r;
}
__device__ __forceinline__ uint32_t hadd2u(uint32_t a, uint32_t b) {
    uint32_t r;
    asm("add.rn.f16x2 %0, %1, %2;" : "=r"(r) : "r"(a), "r"(b));
    return r;
}
__device__ __forceinline__ uint32_t hfma2u(uint32_t a, uint32_t b, uint32_t c) {
    uint32_t r;
    asm("fma.rn.f16x2 %0, %1, %2, %3;" : "=r"(r) : "r"(a), "r"(b), "r"(c));
    return r;
}
__device__ __forceinline__ float h2sum(uint32_t v) {
    __half2 h = *reinterpret_cast<__half2*>(&v);
    return __low2float(h) + __high2float(h);
}
// exact-ish sigmoid(2v) = (tanh(v)+1)/2
__device__ __forceinline__ float fast_sigmoid2(float v) {
    float e, r;
    asm("ex2.approx.f32 %0, %1;" : "=f"(e) : "f"(-2.885390081777927f * v));
    asm("rcp.approx.f32 %0, %1;" : "=f"(r) : "f"(1.0f + e));
    return r;
}

__device__ __forceinline__ void mma16816(float& c0, float& c1, float& c2, float& c3,
                                         uint32_t a0, uint32_t a1, uint32_t a2, uint32_t a3,
                                         uint32_t b0, uint32_t b1) {
    asm volatile(
        "mma.sync.aligned.m16n8k16.row.col.f32.f16.f16.f32 "
        "{%0,%1,%2,%3}, {%4,%5,%6,%7}, {%8,%9}, {%0,%1,%2,%3};"
        : "+f"(c0), "+f"(c1), "+f"(c2), "+f"(c3)
        : "r"(a0), "r"(a1), "r"(a2), "r"(a3), "r"(b0), "r"(b1));
}

// ---------------- kernels ----------------
__global__ void sel_reset_kernel() { g_task_ctr = 0u; }

__global__ void __launch_bounds__(THREADS, 2) sel_main_kernel(
    const float* __restrict__ x,    // [B, 64]
    const float* __restrict__ W1,   // [8,32,64] flat: n*64 + i  (n = kc*32+h)
    const float* __restrict__ b1v,  // [256]
    const float* __restrict__ W2v,  // [256]
    const float* __restrict__ b2v,  // [8]
    float* __restrict__ out)        // [B, 8]
{
    extern __shared__ char smem[];
    uint4* bfrag = (uint4*)(smem + OFF_BFRAG);
    uint4* b1f   = (uint4*)(smem + OFF_B1F);
    uint4* w2f   = (uint4*)(smem + OFF_W2F);

    const int tid  = threadIdx.x;
    const int lane = tid & 31;
    const int wid  = tid >> 5;
    const int g    = lane >> 2;   // group id (row within 8)
    const int tg   = lane & 3;    // thread in group (col pair)

    // ---- build W1 B-fragments in smem (once per CTA) ----
    // bfrag[((kc*4+ks)*2+ntp)*32 + l] = uint4{ b0(nt=2ntp), b1(nt=2ntp),
    //                                          b0(nt=2ntp+1), b1(nt=2ntp+1) }
    // where for lane l (lg=l>>2, ltg=l&3):
    //   b0 = {W1[n][k0], W1[n][k0+1]},  b1 = {W1[n][k0+8], W1[n][k0+9]}
    //   k0 = ks*16 + ltg*2, n = kc*32 + nt*8 + lg
    for (int idx = tid; idx < 2048; idx += THREADS) {
        int l = idx & 31;
        int rest = idx >> 5;            // kc*8 + ks*2 + ntp
        int ntp = rest & 1;
        int ks = (rest >> 1) & 3;
        int kc = rest >> 3;
        int lg = l >> 2, ltg = l & 3;
        int k0 = ks * 16 + ltg * 2;
        uint32_t v[4];
        #pragma unroll
        for (int j = 0; j < 2; j++) {
            int n = kc * 32 + (ntp * 2 + j) * 8 + lg;
            const float* wp = W1 + n * 64 + k0;
            float2 p0 = *(const float2*)wp;
            float2 p1 = *(const float2*)(wp + 8);
            v[j * 2 + 0] = pack_h2(p0.x, p0.y);
            v[j * 2 + 1] = pack_h2(p1.x, p1.y);
        }
        bfrag[idx] = make_uint4(v[0], v[1], v[2], v[3]);
    }
    // b1 / W2 fragment arrays: [kc*32 + l] -> 4 x f16x2 (nt = 0..3), cols ltg*2,+1
    for (int idx = tid; idx < 256; idx += THREADS) {
        int l = idx & 31, kc = idx >> 5;
        int ltg = l & 3;
        uint32_t bv[4], wv[4];
        #pragma unroll
        for (int nt = 0; nt < 4; nt++) {
            int n = kc * 32 + nt * 8 + ltg * 2;
            float2 bb = *(const float2*)(b1v + n);
            float2 ww = *(const float2*)(W2v + n);
            bv[nt] = pack_h2(bb.x, bb.y);
            wv[nt] = pack_h2(ww.x, ww.y);
        }
        b1f[idx] = make_uint4(bv[0], bv[1], bv[2], bv[3]);
        w2f[idx] = make_uint4(wv[0], wv[1], wv[2], wv[3]);
    }
    float b2r[8];
    #pragma unroll
    for (int kc = 0; kc < 8; kc++) b2r[kc] = b2v[kc];
    __syncthreads();

    uint32_t* xs = (uint32_t*)(smem + OFF_XST + (unsigned)wid * XST_STRIDE);

    // ---- warp-autonomous task loop: 32 rows per task ----
    for (;;) {
        unsigned t;
        if (lane == 0) t = atomicAdd(&g_task_ctr, 1u);
        t = __shfl_sync(0xFFFFFFFFu, t, 0);
        if (t >= N_TASKS) break;

        const size_t rowbase = (size_t)t * 32;

        // stage x[32 rows x 64] as f16x2, row stride 36 u32 (pad: conflict-free frags)
        const float4* xg = (const float4*)(x + rowbase * 64);
        #pragma unroll
        for (int it = 0; it < 16; it++) {
            float4 f = xg[it * 32 + lane];
            int fi = (it * 32 + lane) * 4;
            int row = fi >> 6;
            int cp = (fi & 63) >> 1;     // even
            xs[row * 36 + cp]     = pack_h2(f.x, f.y);
            xs[row * 36 + cp + 1] = pack_h2(f.z, f.w);
        }
        __syncwarp();

        // A fragments: [rb][ks][4], rows rb*16 + {g, g+8}, col pairs ks*8+tg, +4
        uint32_t A[2][4][4];
        #pragma unroll
        for (int rb = 0; rb < 2; rb++) {
            #pragma unroll
            for (int ks = 0; ks < 4; ks++) {
                int r0 = rb * 16 + g;
                int r1 = r0 + 8;
                int cp0 = ks * 8 + tg;
                A[rb][ks][0] = xs[r0 * 36 + cp0];
                A[rb][ks][1] = xs[r1 * 36 + cp0];
                A[rb][ks][2] = xs[r0 * 36 + cp0 + 4];
                A[rb][ks][3] = xs[r1 * 36 + cp0 + 4];
            }
        }
        __syncwarp();                       // xs now reusable as out-stage
        float* ostage = (float*)xs;         // 256 floats

        #pragma unroll
        for (int kc = 0; kc < 8; kc++) {
            float c[2][4][4];
            #pragma unroll
            for (int rb = 0; rb < 2; rb++)
                #pragma unroll
                for (int nt = 0; nt < 4; nt++)
                    #pragma unroll
                    for (int q = 0; q < 4; q++) c[rb][nt][q] = 0.0f;

            #pragma unroll
            for (int ks = 0; ks < 4; ks++) {
                #pragma unroll
                for (int ntp = 0; ntp < 2; ntp++) {
                    uint4 bf = bfrag[((kc * 4 + ks) * 2 + ntp) * 32 + lane];
                    #pragma unroll
                    for (int rb = 0; rb < 2; rb++) {
                        mma16816(c[rb][ntp*2+0][0], c[rb][ntp*2+0][1],
                                 c[rb][ntp*2+0][2], c[rb][ntp*2+0][3],
                                 A[rb][ks][0], A[rb][ks][1], A[rb][ks][2], A[rb][ks][3],
                                 bf.x, bf.y);
                        mma16816(c[rb][ntp*2+1][0], c[rb][ntp*2+1][1],
                                 c[rb][ntp*2+1][2], c[rb][ntp*2+1][3],
                                 A[rb][ks][0], A[rb][ks][1], A[rb][ks][2], A[rb][ks][3],
                                 bf.z, bf.w);
                    }
                }
            }

            // epilogue: th = tanh(h + b1); acc = sum th*W2 ; out = sigmoid(2(acc+b2))
            uint4 bb = b1f[kc * 32 + lane];
            uint4 ww = w2f[kc * 32 + lane];
            #pragma unroll
            for (int rb = 0; rb < 2; rb++) {
                uint32_t accA = 0u, accB = 0u;   // f16x2 zero
                #pragma unroll
                for (int nt = 0; nt < 4; nt++) {
                    uint32_t b2h = (nt == 0) ? bb.x : (nt == 1) ? bb.y : (nt == 2) ? bb.z : bb.w;
                    uint32_t w2h = (nt == 0) ? ww.x : (nt == 1) ? ww.y : (nt == 2) ? ww.z : ww.w;
                    // row g:   c0 (col even), c1 (col odd); row g+8: c2, c3
                    uint32_t pA = hadd2u(pack_h2(c[rb][nt][0], c[rb][nt][1]), b2h);
                    uint32_t pB = hadd2u(pack_h2(c[rb][nt][2], c[rb][nt][3]), b2h);
                    accA = hfma2u(tanh2u(pA), w2h, accA);
                    accB = hfma2u(tanh2u(pB), w2h, accB);
                }
                float vA = h2sum(accA);
                float vB = h2sum(accB);
                vA += __shfl_xor_sync(0xFFFFFFFFu, vA, 1);
                vA += __shfl_xor_sync(0xFFFFFFFFu, vA, 2);
                vB += __shfl_xor_sync(0xFFFFFFFFu, vB, 1);
                vB += __shfl_xor_sync(0xFFFFFFFFu, vB, 2);
                if (tg == 0) {
                    int rA = rb * 16 + g;
                    ostage[rA * 8 + kc]       = fast_sigmoid2(vA + b2r[kc]);
                    ostage[(rA + 8) * 8 + kc] = fast_sigmoid2(vB + b2r[kc]);
                }
            }
        }
        __syncwarp();

        // coalesced store: 32 rows x 8 floats = 64 float4, contiguous
        float4* og = (float4*)(out + rowbase * 8);
        float4* os4 = (float4*)ostage;
        og[lane]      = os4[lane];
        og[lane + 32] = os4[lane + 32];
        __syncwarp();   // before next iteration overwrites xs
    }
}

// ---------------- launch ----------------
extern "C" void kernel_launch(void* const* d_in, const int* in_sizes, int n_in,
                              void* d_out, int out_size) {
    const float* x  = (const float*)d_in[0];
    const float* W1 = (const float*)d_in[1];
    const float* b1 = (const float*)d_in[2];
    const float* W2 = (const float*)d_in[3];
    const float* b2 = (const float*)d_in[4];
    float* out = (float*)d_out;

    cudaFuncSetAttribute(sel_main_kernel,
                         cudaFuncAttributeMaxDynamicSharedMemorySize, SMEM_BYTES);

    sel_reset_kernel<<<1, 1>>>();
    sel_main_kernel<<<GRID_CTAS, THREADS, SMEM_BYTES>>>(x, W1, b1, W2, b2, out);
}

// round 3
// speedup vs baseline: 1.1855x; 1.1855x over previous
#include <cuda_runtime.h>
#include <cuda_fp16.h>
#include <cstdint>

// ---------------- problem constants ----------------
#define B_ROWS   524288
#define N_TASKS  16384          // 32 rows per warp-task
#define THREADS  256            // 8 warps
#define GRID_CTAS 296

// smem layout (bytes)
#define OFF_BFRAG 0u            // 2048 x uint4 = 32768  (W1 fp16 B-fragments)
#define OFF_B1S   32768u        // 256 x f32 = 1024
#define OFF_XST   33792u        // 8 warps x 4608B x-stage (32 rows x 144B)
#define XST_STRIDE 4608u
#define SMEM_BYTES 70656u

static __device__ unsigned int g_task_ctr;

// ---------------- helpers ----------------
__device__ __forceinline__ uint32_t smem_u32(const void* p) {
    uint32_t a;
    asm("{ .reg .u64 t; cvta.to.shared.u64 t, %1; cvt.u32.u64 %0, t; }"
        : "=r"(a) : "l"(p));
    return a;
}
// pack two f32 -> f16x2 {lo, hi}
__device__ __forceinline__ uint32_t pack_h2(float lo, float hi) {
    uint32_t r;
    asm("cvt.rn.f16x2.f32 %0, %1, %2;" : "=r"(r) : "f"(hi), "f"(lo));
    return r;
}
__device__ __forceinline__ uint32_t tanh2u(uint32_t v) {
    uint32_t r;
    asm("tanh.approx.f16x2 %0, %1;" : "=r"(r) : "r"(v));
    return r;
}
// (tanh(v)+1)/2 = sigmoid(2v)
__device__ __forceinline__ float fast_sigmoid2(float v) {
    float e, r;
    asm("ex2.approx.f32 %0, %1;" : "=f"(e) : "f"(-2.885390081777927f * v));
    asm("rcp.approx.f32 %0, %1;" : "=f"(r) : "f"(1.0f + e));
    return r;
}
__device__ __forceinline__ void mma16816(float& c0, float& c1, float& c2, float& c3,
                                         uint32_t a0, uint32_t a1, uint32_t a2, uint32_t a3,
                                         uint32_t b0, uint32_t b1) {
    asm volatile(
        "mma.sync.aligned.m16n8k16.row.col.f32.f16.f16.f32 "
        "{%0,%1,%2,%3}, {%4,%5,%6,%7}, {%8,%9}, {%0,%1,%2,%3};"
        : "+f"(c0), "+f"(c1), "+f"(c2), "+f"(c3)
        : "r"(a0), "r"(a1), "r"(a2), "r"(a3), "r"(b0), "r"(b1));
}

// ---------------- kernels ----------------
__global__ void sel_reset_kernel() { g_task_ctr = 0u; }

__global__ void __launch_bounds__(THREADS, 2) sel_main_kernel(
    const float* __restrict__ x,    // [B, 64]
    const float* __restrict__ W1,   // [8,32,64] flat: n*64 + i  (n = kc*32+h)
    const float* __restrict__ b1v,  // [256]
    const float* __restrict__ W2v,  // [256]
    const float* __restrict__ b2v,  // [8]
    float* __restrict__ out)        // [B, 8]
{
    extern __shared__ char smem[];
    uint4*  bfrag = (uint4*)(smem + OFF_BFRAG);
    float*  b1s   = (float*)(smem + OFF_B1S);

    const int tid  = threadIdx.x;
    const int lane = tid & 31;
    const int wid  = tid >> 5;
    const int g    = lane >> 2;   // group id (row within 8 / B n-col / out col owner)
    const int tg   = lane & 3;    // thread in group

    // ---- build W1 B-fragments in smem (once per CTA) ----
    // layout confirmed by R2-passing kernel: b0={W1[n][k0],W1[n][k0+1]},
    // b1={W1[n][k0+8],W1[n][k0+9]}, k0=ltg*2+ks*16, n=kc*32+nt*8+lg
    for (int idx = tid; idx < 2048; idx += THREADS) {
        int l = idx & 31;
        int rest = idx >> 5;            // kc*8 + ks*2 + ntp
        int ntp = rest & 1;
        int ks = (rest >> 1) & 3;
        int kc = rest >> 3;
        int lg = l >> 2, ltg = l & 3;
        int k0 = ks * 16 + ltg * 2;
        uint32_t v[4];
        #pragma unroll
        for (int j = 0; j < 2; j++) {
            int n = kc * 32 + (ntp * 2 + j) * 8 + lg;
            const float* wp = W1 + n * 64 + k0;
            float2 p0 = *(const float2*)wp;
            float2 p1 = *(const float2*)(wp + 8);
            v[j * 2 + 0] = pack_h2(p0.x, p0.y);
            v[j * 2 + 1] = pack_h2(p1.x, p1.y);
        }
        bfrag[idx] = make_uint4(v[0], v[1], v[2], v[3]);
    }
    for (int idx = tid; idx < 256; idx += THREADS)
        b1s[idx] = b1v[idx];
    __syncthreads();

    // ---- per-lane persistent constants ----
    // W2 B-frags for the out-mma (nonzero only when this lane's g == kc):
    // w2r[p*2+j] = pack(W2[g][p*16 + j*8 + 2tg], W2[g][p*16 + j*8 + 2tg + 1])
    uint32_t w2r[4];
    #pragma unroll
    for (int p = 0; p < 2; p++)
        #pragma unroll
        for (int j = 0; j < 2; j++) {
            float2 ww = *(const float2*)(W2v + g * 32 + p * 16 + j * 8 + 2 * tg);
            w2r[p * 2 + j] = pack_h2(ww.x, ww.y);
        }
    const float2 b2p = *(const float2*)(b2v + 2 * tg);

    uint32_t* xs = (uint32_t*)(smem + OFF_XST + (unsigned)wid * XST_STRIDE);
    const uint32_t xsb = smem_u32(xs);
    // ldmatrix per-lane address component
    const int lm = lane >> 3, lr = lane & 7;
    const uint32_t lmoff = (uint32_t)(((lm & 1) * 8 + lr) * 144 + (lm >> 1) * 16);

    // ---- warp-autonomous task loop: 32 rows per task ----
    for (;;) {
        unsigned t;
        if (lane == 0) t = atomicAdd(&g_task_ctr, 1u);
        t = __shfl_sync(0xFFFFFFFFu, t, 0);
        if (t >= N_TASKS) break;

        const size_t rowbase = (size_t)t * 32;

        // stage x[32 x 64] as f16, row stride 144B (pad: conflict-free)
        const float4* xg = (const float4*)(x + rowbase * 64);
        #pragma unroll
        for (int it = 0; it < 16; it++) {
            float4 f = xg[it * 32 + lane];
            int fi = (it * 32 + lane) * 4;
            int row = fi >> 6;
            int cp = (fi & 63) >> 1;
            *(uint2*)(xs + row * 36 + cp) =
                make_uint2(pack_h2(f.x, f.y), pack_h2(f.z, f.w));
        }
        __syncwarp();

        // A fragments via ldmatrix.x4: tile (rb, ks) = rows rb*16+0..15, k ks*16+0..15
        uint32_t A[2][4][4];
        #pragma unroll
        for (int rb = 0; rb < 2; rb++)
            #pragma unroll
            for (int ks = 0; ks < 4; ks++) {
                uint32_t addr = xsb + (uint32_t)(rb * 2304 + ks * 32) + lmoff;
                asm volatile(
                    "ldmatrix.sync.aligned.m8n8.x4.shared.b16 {%0,%1,%2,%3}, [%4];"
                    : "=r"(A[rb][ks][0]), "=r"(A[rb][ks][1]),
                      "=r"(A[rb][ks][2]), "=r"(A[rb][ks][3])
                    : "r"(addr));
            }

        // out accumulators D[32 x 8], init with b2 (C frag: c0=C[g][2tg], c1=+1,
        // c2=C[g+8][2tg], c3=+1)
        float d[2][4];
        #pragma unroll
        for (int rb = 0; rb < 2; rb++) {
            d[rb][0] = b2p.x; d[rb][1] = b2p.y;
            d[rb][2] = b2p.x; d[rb][3] = b2p.y;
        }

        #pragma unroll
        for (int kc = 0; kc < 8; kc++) {
            // accumulators pre-loaded with b1 (f32)
            float c[2][4][4];
            #pragma unroll
            for (int nt = 0; nt < 4; nt++) {
                float2 bb = *(const float2*)(b1s + kc * 32 + nt * 8 + 2 * tg);
                #pragma unroll
                for (int rb = 0; rb < 2; rb++) {
                    c[rb][nt][0] = bb.x; c[rb][nt][1] = bb.y;
                    c[rb][nt][2] = bb.x; c[rb][nt][3] = bb.y;
                }
            }

            // GEMM1: h = x @ W1_kc^T (+b1 via init)
            #pragma unroll
            for (int ks = 0; ks < 4; ks++)
                #pragma unroll
                for (int ntp = 0; ntp < 2; ntp++) {
                    uint4 bf = bfrag[((kc * 4 + ks) * 2 + ntp) * 32 + lane];
                    #pragma unroll
                    for (int rb = 0; rb < 2; rb++) {
                        mma16816(c[rb][ntp*2+0][0], c[rb][ntp*2+0][1],
                                 c[rb][ntp*2+0][2], c[rb][ntp*2+0][3],
                                 A[rb][ks][0], A[rb][ks][1], A[rb][ks][2], A[rb][ks][3],
                                 bf.x, bf.y);
                        mma16816(c[rb][ntp*2+1][0], c[rb][ntp*2+1][1],
                                 c[rb][ntp*2+1][2], c[rb][ntp*2+1][3],
                                 A[rb][ks][0], A[rb][ks][1], A[rb][ks][2], A[rb][ks][3],
                                 bf.z, bf.w);
                    }
                }

            // GEMM2 via tensor core: D[:, kc] += tanh(h) @ W2_kc.
            // B nonzero only in column n == kc; per-lane (n = g) select.
            uint32_t B0p0 = (g == kc) ? w2r[0] : 0u;
            uint32_t B1p0 = (g == kc) ? w2r[1] : 0u;
            uint32_t B0p1 = (g == kc) ? w2r[2] : 0u;
            uint32_t B1p1 = (g == kc) ? w2r[3] : 0u;
            #pragma unroll
            for (int rb = 0; rb < 2; rb++) {
                // k-block p: th A-frag = repacked C-frags of nt=2p, 2p+1
                uint32_t ta0, ta1, ta2, ta3;
                // p = 0
                ta0 = tanh2u(pack_h2(c[rb][0][0], c[rb][0][1]));
                ta1 = tanh2u(pack_h2(c[rb][0][2], c[rb][0][3]));
                ta2 = tanh2u(pack_h2(c[rb][1][0], c[rb][1][1]));
                ta3 = tanh2u(pack_h2(c[rb][1][2], c[rb][1][3]));
                mma16816(d[rb][0], d[rb][1], d[rb][2], d[rb][3],
                         ta0, ta1, ta2, ta3, B0p0, B1p0);
                // p = 1
                ta0 = tanh2u(pack_h2(c[rb][2][0], c[rb][2][1]));
                ta1 = tanh2u(pack_h2(c[rb][2][2], c[rb][2][3]));
                ta2 = tanh2u(pack_h2(c[rb][3][0], c[rb][3][1]));
                ta3 = tanh2u(pack_h2(c[rb][3][2], c[rb][3][3]));
                mma16816(d[rb][0], d[rb][1], d[rb][2], d[rb][3],
                         ta0, ta1, ta2, ta3, B0p1, B1p1);
            }
        }

        // final: out = sigmoid(2*(D)) ; C frag -> coalesced float2 stores
        #pragma unroll
        for (int rb = 0; rb < 2; rb++) {
            float* orow = out + (rowbase + (unsigned)(rb * 16 + g)) * 8 + 2 * tg;
            *(float2*)orow =
                make_float2(fast_sigmoid2(d[rb][0]), fast_sigmoid2(d[rb][1]));
            *(float2*)(orow + 64) =
                make_float2(fast_sigmoid2(d[rb][2]), fast_sigmoid2(d[rb][3]));
        }
        __syncwarp();   // xs reuse guard before next task's stores
    }
}

// ---------------- launch ----------------
extern "C" void kernel_launch(void* const* d_in, const int* in_sizes, int n_in,
                              void* d_out, int out_size) {
    const float* x  = (const float*)d_in[0];
    const float* W1 = (const float*)d_in[1];
    const float* b1 = (const float*)d_in[2];
    const float* W2 = (const float*)d_in[3];
    const float* b2 = (const float*)d_in[4];
    float* out = (float*)d_out;

    cudaFuncSetAttribute(sel_main_kernel,
                         cudaFuncAttributeMaxDynamicSharedMemorySize, SMEM_BYTES);

    sel_reset_kernel<<<1, 1>>>();
    sel_main_kernel<<<GRID_CTAS, THREADS, SMEM_BYTES>>>(x, W1, b1, W2, b2, out);
}